// round 6
// baseline (speedup 1.0000x reference)
#include <cuda_runtime.h>
#include <stdint.h>

// ---------------- static scratch (no runtime alloc allowed) ----------------
#define MAXN 100000
#define MAXE 3200000

__device__ __align__(16) float g_c1out[MAXN * 64];          // [N, 64]  xl_c1 | xr_c1
__device__ __align__(16) float g_h1[MAXN * 32];             // [N, 32]
__device__ __align__(16) float g_c2out[(size_t)MAXN * 256]; // [N,256] xl_c2 | xr_c2
__device__ __align__(16) float g_h2[MAXN * 128];            // [N,128]
__device__ __align__(16) float g_c3out[MAXN * 128];         // [N,128] mu_l|mu_r|ls_l|ls_r
__device__ __align__(16) float g_Wpack[512 * 64];           // packed weights (reused)
__device__ int g_counts[MAXN];
__device__ int g_fill[MAXN];
__device__ int g_rowptr[MAXN + 1];
__device__ int g_srcs[MAXE];
__device__ int g_blockSums[256];
__device__ int g_isI64;

// ---------------- helpers ----------------
__device__ __forceinline__ float warpSum(float v) {
#pragma unroll
    for (int o = 16; o > 0; o >>= 1) v += __shfl_xor_sync(0xffffffffu, v, o);
    return v;
}

__device__ __forceinline__ float lk(float v) { return v > 0.f ? v : 0.2f * v; }

// dtype-aware edge-index accessor (int32 vs int64 decided at runtime on device)
__device__ __forceinline__ int edgeIdx(const void* p, long long i) {
    if (g_isI64) return (int)((const long long*)p)[i];
    return ((const int*)p)[i];
}

// ---------------- dtype probe ----------------
__global__ void k_probe(const unsigned int* __restrict__ w) {
    if (threadIdx.x == 0 && blockIdx.x == 0) {
        int allz = 1;
        for (int i = 0; i < 32; i++) allz &= (w[2 * i + 1] == 0u);
        g_isI64 = allz;
    }
}

// ---------------- CSR build ----------------
__global__ void k_zero2(int n) {
    int i = blockIdx.x * blockDim.x + threadIdx.x;
    if (i < n) { g_counts[i] = 0; g_fill[i] = 0; }
}

__global__ void k_hist(const void* __restrict__ ei, int E, int N) {
    int e = blockIdx.x * blockDim.x + threadIdx.x;
    if (e < E) {
        int d = edgeIdx(ei, (long long)E + e);  // dst row
        if ((unsigned)d < (unsigned)N) atomicAdd(&g_counts[d], 1);
    }
}

__global__ void k_scan1(int n) {  // block=1024
    __shared__ int sm[1024];
    int tid = threadIdx.x;
    int i = blockIdx.x * 1024 + tid;
    int v = (i < n) ? g_counts[i] : 0;
    sm[tid] = v;
    __syncthreads();
#pragma unroll
    for (int off = 1; off < 1024; off <<= 1) {
        int add = (tid >= off) ? sm[tid - off] : 0;
        __syncthreads();
        sm[tid] += add;
        __syncthreads();
    }
    if (i < n) g_rowptr[i] = sm[tid] - v;  // exclusive within block
    if (tid == 1023) g_blockSums[blockIdx.x] = sm[1023];
}

__global__ void k_scan2(int nb) {
    if (threadIdx.x == 0 && blockIdx.x == 0) {
        int run = 0;
        for (int b = 0; b < nb; b++) { int t = g_blockSums[b]; g_blockSums[b] = run; run += t; }
    }
}

__global__ void k_scan3(int n, int E) {
    int i = blockIdx.x * blockDim.x + threadIdx.x;
    if (i < n) g_rowptr[i] += g_blockSums[i >> 10];
    if (i == 0) g_rowptr[n] = E;
}

__global__ void k_scatter(const void* __restrict__ ei, int E, int N) {
    int e = blockIdx.x * blockDim.x + threadIdx.x;
    if (e < E) {
        int d = edgeIdx(ei, (long long)E + e);
        int s = edgeIdx(ei, e);
        if ((unsigned)d < (unsigned)N && (unsigned)s < (unsigned)N) {
            int p = g_rowptr[d] + atomicAdd(&g_fill[d], 1);
            g_srcs[p] = s;
        }
    }
}

// ---------------- weight packing ----------------
__global__ void k_pack2(const float* __restrict__ Wl, const float* __restrict__ Wr,
                        int K, int D) {
    int i = blockIdx.x * blockDim.x + threadIdx.x;
    if (i >= K * D) return;
    int k = i / D, d = i % D;
    g_Wpack[k * 2 * D + d]     = Wl[i];
    g_Wpack[k * 2 * D + D + d] = Wr[i];
}

__global__ void k_pack4(const float* __restrict__ W0, const float* __restrict__ W1,
                        const float* __restrict__ W2, const float* __restrict__ W3,
                        int K) {  // D = 32 each
    int i = blockIdx.x * blockDim.x + threadIdx.x;
    if (i >= K * 32) return;
    int k = i / 32, d = i % 32;
    g_Wpack[k * 128 + d]       = W0[i];
    g_Wpack[k * 128 + 32 + d]  = W1[i];
    g_Wpack[k * 128 + 64 + d]  = W2[i];
    g_Wpack[k * 128 + 96 + d]  = W3[i];
}

// ---------------- SGEMM: C[M,Nn] = A[M,K] @ g_Wpack[K,Nn] ----------------
// BM=128 BN=64 BK=16, 256 threads, TM=8 TN=4
template <int LAYER>
__global__ __launch_bounds__(256) void k_sgemm(const float* __restrict__ Aext,
                                               int M, int Nn, int K) {
    const float* __restrict__ A = (LAYER == 0) ? Aext : (LAYER == 1 ? g_h1 : g_h2);
    float* __restrict__ C = (LAYER == 0) ? g_c1out : (LAYER == 1 ? g_c2out : g_c3out);
    const float* __restrict__ B = g_Wpack;

    __shared__ float As[16][128];
    __shared__ float Bs[16][64];
    const int rowBase = blockIdx.x * 128;
    const int colBase = blockIdx.y * 64;
    const int t = threadIdx.x;
    const int tx = t & 15;   // col group (4 cols)
    const int ty = t >> 4;   // row group (8 rows)
    float acc[8][4];
#pragma unroll
    for (int i = 0; i < 8; i++)
#pragma unroll
        for (int j = 0; j < 4; j++) acc[i][j] = 0.f;

    for (int k0 = 0; k0 < K; k0 += 16) {
#pragma unroll
        for (int i = 0; i < 2; i++) {
            int f = t + i * 256;
            int r = f >> 2, c4 = f & 3;
            int grow = rowBase + r;
            float4 v = make_float4(0.f, 0.f, 0.f, 0.f);
            if (grow < M)
                v = *reinterpret_cast<const float4*>(A + (size_t)grow * K + k0 + c4 * 4);
            As[c4 * 4 + 0][r] = v.x;
            As[c4 * 4 + 1][r] = v.y;
            As[c4 * 4 + 2][r] = v.z;
            As[c4 * 4 + 3][r] = v.w;
        }
        {
            int kk = t >> 4, c4 = t & 15;
            float4 v = *reinterpret_cast<const float4*>(B + (size_t)(k0 + kk) * Nn + colBase + c4 * 4);
            *reinterpret_cast<float4*>(&Bs[kk][c4 * 4]) = v;
        }
        __syncthreads();
#pragma unroll
        for (int k = 0; k < 16; k++) {
            float ra[8], rb[4];
#pragma unroll
            for (int i = 0; i < 8; i++) ra[i] = As[k][ty * 8 + i];
#pragma unroll
            for (int j = 0; j < 4; j++) rb[j] = Bs[k][tx * 4 + j];
#pragma unroll
            for (int i = 0; i < 8; i++)
#pragma unroll
                for (int j = 0; j < 4; j++) acc[i][j] = fmaf(ra[i], rb[j], acc[i][j]);
        }
        __syncthreads();
    }
#pragma unroll
    for (int i = 0; i < 8; i++) {
        int grow = rowBase + ty * 8 + i;
        if (grow < M) {
            float4 v = make_float4(acc[i][0], acc[i][1], acc[i][2], acc[i][3]);
            *reinterpret_cast<float4*>(C + (size_t)grow * Nn + colBase + tx * 4) = v;
        }
    }
}

// ---------------- GATv2 edge kernels (warp per dst node, online softmax) ----------------
__global__ void k_gat32(const float* __restrict__ att, const float* __restrict__ bias, int N) {
    int warp = (blockIdx.x * blockDim.x + threadIdx.x) >> 5;
    int lane = threadIdx.x & 31;
    if (warp >= N) return;
    float attk = att[lane];
    float bk = bias[lane];
    const float* xin = g_c1out;
    float xrk = xin[(size_t)warp * 64 + 32 + lane];
    float xlk0 = xin[(size_t)warp * 64 + lane];
    float m = warpSum(lk(xlk0 + xrk) * attk);
    float ssum = 1.f, acc = xlk0;
    int beg = g_rowptr[warp], end = g_rowptr[warp + 1];
    for (int j0 = beg; j0 < end; j0 += 32) {
        int mysrc = (j0 + lane < end) ? g_srcs[j0 + lane] : 0;
        int cnt = min(32, end - j0);
        for (int u = 0; u < cnt; ++u) {
            int src = __shfl_sync(0xffffffffu, mysrc, u);
            float xlk = xin[(size_t)src * 64 + lane];
            float ee = warpSum(lk(xlk + xrk) * attk);
            float mn = fmaxf(m, ee);
            float c = __expf(m - mn), p = __expf(ee - mn);
            ssum = ssum * c + p;
            acc = fmaf(p, xlk, acc * c);
            m = mn;
        }
    }
    float o = acc / (ssum + 1e-16f) + bk;
    o = o > 0.f ? o : expm1f(o);
    g_h1[(size_t)warp * 32 + lane] = o;
}

__global__ void k_gat128(const float* __restrict__ att, const float* __restrict__ bias, int N) {
    int warp = (blockIdx.x * blockDim.x + threadIdx.x) >> 5;
    int lane = threadIdx.x & 31;
    if (warp >= N) return;
    const float4* base = reinterpret_cast<const float4*>(g_c2out);
    float4 attk = reinterpret_cast<const float4*>(att)[lane];
    float4 bk = reinterpret_cast<const float4*>(bias)[lane];
    float4 xr4 = base[(size_t)warp * 64 + 32 + lane];
    float4 xl4 = base[(size_t)warp * 64 + lane];
    float t0 = lk(xl4.x + xr4.x) * attk.x + lk(xl4.y + xr4.y) * attk.y +
               lk(xl4.z + xr4.z) * attk.z + lk(xl4.w + xr4.w) * attk.w;
    float m = warpSum(t0);
    float ssum = 1.f;
    float4 acc = xl4;
    int beg = g_rowptr[warp], end = g_rowptr[warp + 1];
    for (int j0 = beg; j0 < end; j0 += 32) {
        int mysrc = (j0 + lane < end) ? g_srcs[j0 + lane] : 0;
        int cnt = min(32, end - j0);
        for (int u = 0; u < cnt; ++u) {
            int src = __shfl_sync(0xffffffffu, mysrc, u);
            float4 v = base[(size_t)src * 64 + lane];
            float tt = lk(v.x + xr4.x) * attk.x + lk(v.y + xr4.y) * attk.y +
                       lk(v.z + xr4.z) * attk.z + lk(v.w + xr4.w) * attk.w;
            float ee = warpSum(tt);
            float mn = fmaxf(m, ee);
            float c = __expf(m - mn), p = __expf(ee - mn);
            ssum = ssum * c + p;
            acc.x = fmaf(p, v.x, acc.x * c);
            acc.y = fmaf(p, v.y, acc.y * c);
            acc.z = fmaf(p, v.z, acc.z * c);
            acc.w = fmaf(p, v.w, acc.w * c);
            m = mn;
        }
    }
    float inv = 1.f / (ssum + 1e-16f);
    float4 o;
    o.x = acc.x * inv + bk.x; o.y = acc.y * inv + bk.y;
    o.z = acc.z * inv + bk.z; o.w = acc.w * inv + bk.w;
    o.x = o.x > 0.f ? o.x : expm1f(o.x);
    o.y = o.y > 0.f ? o.y : expm1f(o.y);
    o.z = o.z > 0.f ? o.z : expm1f(o.z);
    o.w = o.w > 0.f ? o.w : expm1f(o.w);
    reinterpret_cast<float4*>(g_h2)[(size_t)warp * 32 + lane] = o;
}

__global__ void k_gat_muls(const float* __restrict__ attm, const float* __restrict__ bm,
                           const float* __restrict__ attl, const float* __restrict__ bl,
                           float* __restrict__ outmu, float* __restrict__ outls, int N) {
    int warp = (blockIdx.x * blockDim.x + threadIdx.x) >> 5;
    int lane = threadIdx.x & 31;
    if (warp >= N) return;
    float am = attm[lane], al = attl[lane];
    float bmk = bm[lane], blk = bl[lane];
    const float* row = g_c3out + (size_t)warp * 128;
    float xrm = row[32 + lane], xrl = row[96 + lane];
    float xlm0 = row[lane], xll0 = row[64 + lane];
    float mm = warpSum(lk(xlm0 + xrm) * am);
    float ml = warpSum(lk(xll0 + xrl) * al);
    float sm_ = 1.f, sl_ = 1.f;
    float accm = xlm0, accl = xll0;
    int beg = g_rowptr[warp], end = g_rowptr[warp + 1];
    for (int j0 = beg; j0 < end; j0 += 32) {
        int mysrc = (j0 + lane < end) ? g_srcs[j0 + lane] : 0;
        int cnt = min(32, end - j0);
        for (int u = 0; u < cnt; ++u) {
            int src = __shfl_sync(0xffffffffu, mysrc, u);
            const float* srow = g_c3out + (size_t)src * 128;
            float xm = srow[lane], xl_ = srow[64 + lane];
            float em = warpSum(lk(xm + xrm) * am);
            float el = warpSum(lk(xl_ + xrl) * al);
            float mnm = fmaxf(mm, em);
            float cm = __expf(mm - mnm), pm = __expf(em - mnm);
            sm_ = sm_ * cm + pm; accm = fmaf(pm, xm, accm * cm); mm = mnm;
            float mnl = fmaxf(ml, el);
            float cl = __expf(ml - mnl), pl = __expf(el - mnl);
            sl_ = sl_ * cl + pl; accl = fmaf(pl, xl_, accl * cl); ml = mnl;
        }
    }
    outmu[(size_t)warp * 32 + lane] = accm / (sm_ + 1e-16f) + bmk;
    outls[(size_t)warp * 32 + lane] = accl / (sl_ + 1e-16f) + blk;
}

// ---------------- threefry + normal + z ----------------
__device__ __forceinline__ uint32_t rotl32(uint32_t v, int r) {
    return (v << r) | (v >> (32 - r));
}

__device__ __forceinline__ void threefry2x32(uint32_t k0, uint32_t k1,
                                             uint32_t& x0, uint32_t& x1) {
    uint32_t ks0 = k0, ks1 = k1, ks2 = k0 ^ k1 ^ 0x1BD11BDAu;
    x0 += ks0; x1 += ks1;
#define RND(r) { x0 += x1; x1 = rotl32(x1, r); x1 ^= x0; }
    RND(13) RND(15) RND(26) RND(6)   x0 += ks1; x1 += ks2 + 1u;
    RND(17) RND(29) RND(16) RND(24)  x0 += ks2; x1 += ks0 + 2u;
    RND(13) RND(15) RND(26) RND(6)   x0 += ks0; x1 += ks1 + 3u;
    RND(17) RND(29) RND(16) RND(24)  x0 += ks1; x1 += ks2 + 4u;
    RND(13) RND(15) RND(26) RND(6)   x0 += ks2; x1 += ks0 + 5u;
#undef RND
}

__device__ __forceinline__ float bits_to_normal(uint32_t bits) {
    float f = __uint_as_float((bits >> 9) | 0x3f800000u) - 1.0f;  // [0,1)
    const float lo = -0.99999994f;            // nextafter(-1, 0) in fp32
    const float range = 2.0f;                 // fp32(1 - lo)
    float u = fmaf(f, range, lo);
    u = fmaxf(u, lo);
    return 1.41421356f * erfinvf(u);
}

// JAX threefry_partitionable bit stream (prng.py): counts = iota_2x32_shape ->
// (hi, lo) = (0, i) for sizes < 2^32; (o0, o1) = threefry2x32(key, 0, i);
// 32-bit draw = o0 ^ o1 (the two output lanes XOR-combined).
__global__ void k_z(float* __restrict__ out, int N) {
    int t = blockIdx.x * blockDim.x + threadIdx.x;
    int T = N * 32;
    if (t >= T) return;
    uint32_t x0 = 0u, x1 = (uint32_t)t;
    threefry2x32(0u, 1u, x0, x1);
    float n = bits_to_normal(x0 ^ x1);
    const float* mu = out;
    const float* ls = out + (size_t)N * 32;
    float* z = out + (size_t)2 * N * 32;
    z[t] = n * expf(ls[t]) + mu[t];
}

// ---------------- launch ----------------
extern "C" void kernel_launch(void* const* d_in, const int* in_sizes, int n_in,
                              void* d_out, int out_size) {
    const float* x = (const float*)d_in[0];
    const void* ei = d_in[1];
    const float* Wl_c1 = (const float*)d_in[2];
    const float* Wr_c1 = (const float*)d_in[3];
    const float* att_c1 = (const float*)d_in[4];
    const float* b_c1 = (const float*)d_in[5];
    const float* Wl_c2 = (const float*)d_in[6];
    const float* Wr_c2 = (const float*)d_in[7];
    const float* att_c2 = (const float*)d_in[8];
    const float* b_c2 = (const float*)d_in[9];
    const float* Wl_mu = (const float*)d_in[10];
    const float* Wr_mu = (const float*)d_in[11];
    const float* att_mu = (const float*)d_in[12];
    const float* b_mu = (const float*)d_in[13];
    const float* Wl_ls = (const float*)d_in[14];
    const float* Wr_ls = (const float*)d_in[15];
    const float* att_ls = (const float*)d_in[16];
    const float* b_ls = (const float*)d_in[17];

    const int N = in_sizes[0] / 512;
    const int E = in_sizes[1] / 2;
    float* out = (float*)d_out;

    // ---- edge-index dtype probe + CSR build (by dst) ----
    k_probe<<<1, 32>>>((const unsigned int*)ei);
    k_zero2<<<(N + 255) / 256, 256>>>(N);
    k_hist<<<(E + 255) / 256, 256>>>(ei, E, N);
    int nb = (N + 1023) / 1024;
    k_scan1<<<nb, 1024>>>(N);
    k_scan2<<<1, 32>>>(nb);
    k_scan3<<<(N + 255) / 256, 256>>>(N, E);
    k_scatter<<<(E + 255) / 256, 256>>>(ei, E, N);

    // ---- layer c1: 512 -> 32 ----
    k_pack2<<<(512 * 32 + 255) / 256, 256>>>(Wl_c1, Wr_c1, 512, 32);
    {
        dim3 g((N + 127) / 128, 1);
        k_sgemm<0><<<g, 256>>>(x, N, 64, 512);
    }
    k_gat32<<<(N * 32 + 255) / 256, 256>>>(att_c1, b_c1, N);

    // ---- layer c2: 32 -> 128 ----
    k_pack2<<<(32 * 128 + 255) / 256, 256>>>(Wl_c2, Wr_c2, 32, 128);
    {
        dim3 g((N + 127) / 128, 4);
        k_sgemm<1><<<g, 256>>>(nullptr, N, 256, 32);
    }
    k_gat128<<<(N * 32 + 255) / 256, 256>>>(att_c2, b_c2, N);

    // ---- layers mu / logstd: 128 -> 32 (fused) ----
    k_pack4<<<(128 * 32 + 255) / 256, 256>>>(Wl_mu, Wr_mu, Wl_ls, Wr_ls, 128);
    {
        dim3 g((N + 127) / 128, 2);
        k_sgemm<2><<<g, 256>>>(nullptr, N, 128, 128);
    }
    k_gat_muls<<<(N * 32 + 255) / 256, 256>>>(att_mu, b_mu, att_ls, b_ls,
                                              out, out + (size_t)N * 32, N);

    // ---- reparameterize: z = eps * exp(logstd) + mu ----
    k_z<<<(N * 32 + 255) / 256, 256>>>(out, N);
}